// round 14
// baseline (speedup 1.0000x reference)
#include <cuda_runtime.h>

// Dynamic grouped conv, algebraically reduced (R4 structure):
//   out[b,o,h,w] = sum_{kh,kw} ker[b,o,kh,kw] * S[b,g,h+kh,w+kw]
//   S[b,g] = sum of the 8 input channels of group g (reflection-padded)
//
// R13 == R12 resubmit (container infra failure, no bench data).
// R4 with the interior load loop fully unrolled (exactly 4 iterations
// + 32-thread tail) so ptxas pipelines the 8-LDG batches across iterations
// (MLP ~8 -> ~32 per thread). No cache hints (R9 showed they cost ~2.5us).

static constexpr int HH = 256;
static constexpr int WW = 256;
static constexpr int IN_CH = 64;
static constexpr int OUT_CH = 64;
static constexpr int FPG = 8;
static constexpr int TH = 64;
static constexpr int TW = 64;
static constexpr int SSTR = 72;   // smem row stride in floats (288 B)
// smem col layout: halo(-1) -> 3, interior c -> c+4 (16B aligned), halo(64) -> 68

__device__ __forceinline__ int refl(int i, int n) {
    i = (i < 0) ? -i : i;
    return (i >= n) ? (2 * n - 2 - i) : i;
}

__global__ __launch_bounds__(256, 4)
void dynconv_fused(const float* __restrict__ x,
                   const float* __restrict__ rep,
                   const float* __restrict__ Wm,
                   float* __restrict__ out) {
    __shared__ float S[(TH + 2) * SSTR];
    __shared__ float wk[FPG * 9];

    const int bz = blockIdx.z;             // b*8 + g
    const int b  = bz >> 3;
    const int g  = bz & 7;
    const int ty0 = blockIdx.y * TH;
    const int tx0 = blockIdx.x * TW;
    const int tid = threadIdx.x;

    // ---- threads 0..71: this block's 72 dynamic weights ----
    if (tid < FPG * 9) {
        const int j = (g * FPG) * 9 + tid;          // row of W (576 x 32)
        const float* r = rep + b * 32;
        const float* w = Wm + j * 32;
        float acc = 0.f;
        #pragma unroll
        for (int i = 0; i < 32; i++) acc = fmaf(r[i], w[i], acc);
        wk[tid] = (acc > 0.f) ? acc : 0.1f * acc;
    }

    const float* xb = x + (size_t)(b * IN_CH + g * FPG) * (HH * WW);

    // ---- interior group-sum: 66 rows x 16 float4 = 1056 positions ----
    // exactly 4 unrolled iterations (1024 positions) + 32-thread tail
    #pragma unroll
    for (int i = 0; i < 4; i++) {
        const int pos = tid + i * 256;
        const int r  = pos >> 4;
        const int c4 = pos & 15;
        const int gy = refl(ty0 + r - 1, HH);
        const float4* p = (const float4*)(xb + (size_t)gy * WW + tx0) + c4;
        float4 a = p[0];
        #pragma unroll
        for (int f = 1; f < FPG; f++) {
            float4 v = p[f * (HH * WW / 4)];
            a.x += v.x; a.y += v.y; a.z += v.z; a.w += v.w;
        }
        *(float4*)&S[r * SSTR + 4 + 4 * c4] = a;
    }
    if (tid < 32) {
        const int pos = 1024 + tid;
        const int r  = pos >> 4;
        const int c4 = pos & 15;
        const int gy = refl(ty0 + r - 1, HH);
        const float4* p = (const float4*)(xb + (size_t)gy * WW + tx0) + c4;
        float4 a = p[0];
        #pragma unroll
        for (int f = 1; f < FPG; f++) {
            float4 v = p[f * (HH * WW / 4)];
            a.x += v.x; a.y += v.y; a.z += v.z; a.w += v.w;
        }
        *(float4*)&S[r * SSTR + 4 + 4 * c4] = a;
    }

    // ---- halo columns (global cols tx0-1 and tx0+64): 132 positions ----
    if (tid < 66 * 2) {
        const int r    = tid >> 1;
        const int side = tid & 1;
        const int gy = refl(ty0 + r - 1, HH);
        const int gx = side ? refl(tx0 + 64, WW) : refl(tx0 - 1, WW);
        const float* p = xb + (size_t)gy * WW + gx;
        float a = 0.f;
        #pragma unroll
        for (int f = 0; f < FPG; f++) a += p[f * (HH * WW)];
        S[r * SSTR + (side ? 68 : 3)] = a;
    }
    __syncthreads();

    // ---- mapping: tid = col4(4b) | chq(2b) | rowq(2b) ----
    const int col4 = tid & 15;             // 16 float4 columns
    const int grp  = tid >> 4;
    const int chq  = grp & 3;              // channel pair 2*chq, 2*chq+1
    const int rowq = grp >> 2;             // 4 strips of 16 rows
    const int py0  = rowq * 16;
    const int c0   = 4 * col4;

    float wreg[2][9];
    #pragma unroll
    for (int o = 0; o < 2; o++)
        #pragma unroll
        for (int k = 0; k < 9; k++)
            wreg[o][k] = wk[(chq * 2 + o) * 9 + k];

    float* ob = out + ((size_t)(b * OUT_CH + g * FPG + chq * 2) * HH + ty0) * WW
                    + tx0 + c0;

    // rolling 3-row tap window in registers
    float v[3][6];
    #pragma unroll
    for (int kh = 0; kh < 2; kh++) {
        const float* row = &S[(py0 + kh) * SSTR + c0 + 3];
        v[kh][0] = row[0];
        float4 q = *(const float4*)(row + 1);
        v[kh][1] = q.x; v[kh][2] = q.y; v[kh][3] = q.z; v[kh][4] = q.w;
        v[kh][5] = row[5];
    }

    const float* srow = &S[(py0 + 2) * SSTR + c0 + 3];

    #pragma unroll 4
    for (int j = 0; j < 16; j++) {
        // fetch new bottom row (padded row py0 + j + 2)
        v[2][0] = srow[0];
        {
            float4 q = *(const float4*)(srow + 1);
            v[2][1] = q.x; v[2][2] = q.y; v[2][3] = q.z; v[2][4] = q.w;
        }
        v[2][5] = srow[5];
        srow += SSTR;

        #pragma unroll
        for (int o = 0; o < 2; o++) {
            float4 acc;
            float* ap = (float*)&acc;
            #pragma unroll
            for (int i = 0; i < 4; i++) {
                float a = 0.f;
                #pragma unroll
                for (int kh = 0; kh < 3; kh++)
                    #pragma unroll
                    for (int kw = 0; kw < 3; kw++)
                        a = fmaf(wreg[o][kh * 3 + kw], v[kh][i + kw], a);
                ap[i] = a;
            }
            *(float4*)(ob + (size_t)o * (HH * WW) + (py0 + j) * WW) = acc;
        }

        // rotate window
        #pragma unroll
        for (int t = 0; t < 6; t++) { v[0][t] = v[1][t]; v[1][t] = v[2][t]; }
    }
}

extern "C" void kernel_launch(void* const* d_in, const int* in_sizes, int n_in,
                              void* d_out, int out_size) {
    const float* x   = (const float*)d_in[0];
    const float* rep = (const float*)d_in[1];
    const float* Wm  = (const float*)d_in[2];
    float* out = (float*)d_out;

    dim3 grid(WW / TW, HH / TH, 8 * 8);    // 4 x 4 x 64 = 1024 blocks
    dynconv_fused<<<grid, 256>>>(x, rep, Wm, out);
}

// round 15
// speedup vs baseline: 1.2374x; 1.2374x over previous
#include <cuda_runtime.h>

// Dynamic grouped conv, algebraically reduced:
//   out[b,o,h,w] = sum_{kh,kw} ker[b,o,kh,kw] * S[b,g,h+kh,w+kw]
//   S[b,g] = sum of the 8 input channels of group g (reflection-padded)
//
// R15: intra-CTA software pipeline. Each CTA owns a 64x256 band (4 vertical
// 64x64 tiles), double-buffered SMEM: tile t+1's group-sum loads are issued
// interleaved with tile t's stencil (8 LDG.128 per 4 stencil rows), so the
// read stream and the write stream are concurrently in flight.
// grid=256 CTAs @ 3/SM => single wave.

static constexpr int HH = 256;
static constexpr int WW = 256;
static constexpr int IN_CH = 64;
static constexpr int OUT_CH = 64;
static constexpr int FPG = 8;
static constexpr int TW = 64;
static constexpr int SSTR = 72;               // smem row stride in floats
static constexpr int PLANE  = HH * WW;        // 65536
static constexpr int PLANE4 = PLANE / 4;      // 16384
// smem col layout: halo(-1) -> 3, interior c -> c+4 (16B aligned), halo(64) -> 68

__device__ __forceinline__ int refl(int i, int n) {
    i = (i < 0) ? -i : i;
    return (i >= n) ? (2 * n - 2 - i) : i;
}

__global__ __launch_bounds__(256, 3)
void dynconv_pipe(const float* __restrict__ x,
                  const float* __restrict__ rep,
                  const float* __restrict__ Wm,
                  float* __restrict__ out) {
    __shared__ float S[2][66 * SSTR];          // 2 x 19 KB ping-pong
    __shared__ float wk[FPG * 9];

    const int bz = blockIdx.y;                 // b*8 + g
    const int b  = bz >> 3;
    const int g  = bz & 7;
    const int tx0 = blockIdx.x * TW;
    const int tid = threadIdx.x;

    // ---- threads 0..71: this block's 72 dynamic weights ----
    if (tid < FPG * 9) {
        const int j = (g * FPG) * 9 + tid;     // row of W (576 x 32)
        const float* r = rep + b * 32;
        const float* w = Wm + j * 32;
        float acc = 0.f;
        #pragma unroll
        for (int i = 0; i < 32; i++) acc = fmaf(r[i], w[i], acc);
        wk[tid] = (acc > 0.f) ? acc : 0.1f * acc;
    }

    const float* xb = x + (size_t)(b * IN_CH + g * FPG) * PLANE;

    // ---- tile 0 full load into S[0] (proven R4 ragged-loop form) ----
    for (int pos = tid; pos < 1056; pos += 256) {
        const int r  = pos >> 4;
        const int c4 = pos & 15;
        const int gy = refl(r - 1, HH);
        const float4* p = (const float4*)(xb + (size_t)gy * WW + tx0) + c4;
        float4 a = p[0];
        #pragma unroll
        for (int f = 1; f < FPG; f++) {
            float4 v = p[f * PLANE4];
            a.x += v.x; a.y += v.y; a.z += v.z; a.w += v.w;
        }
        *(float4*)&S[0][r * SSTR + 4 + 4 * c4] = a;
    }
    if (tid < 132) {
        const int r    = tid >> 1;
        const int side = tid & 1;
        const int gy = refl(r - 1, HH);
        const int gx = side ? refl(tx0 + 64, WW) : refl(tx0 - 1, WW);
        const float* p = xb + (size_t)gy * WW + gx;
        float a = 0.f;
        #pragma unroll
        for (int f = 0; f < FPG; f++) a += p[f * PLANE];
        S[0][r * SSTR + (side ? 68 : 3)] = a;
    }
    __syncthreads();

    // ---- stencil mapping: tid = col4(4b) | chq(2b) | rowq(2b) ----
    const int col4 = tid & 15;
    const int grp  = tid >> 4;
    const int chq  = grp & 3;                  // channel pair
    const int rowq = grp >> 2;                 // 4 strips of 16 rows
    const int py0  = rowq * 16;
    const int c0   = 4 * col4;

    float wreg[2][9];
    #pragma unroll
    for (int o = 0; o < 2; o++)
        #pragma unroll
        for (int k = 0; k < 9; k++)
            wreg[o][k] = wk[(chq * 2 + o) * 9 + k];

    #pragma unroll
    for (int t = 0; t < 4; t++) {
        float* Sc = S[t & 1];
        float* Sn = S[(t + 1) & 1];
        const int y0  = t * 64;
        const int ny0 = y0 + 64;
        const bool PREF = (t < 3);

        // rolling 3-row tap window
        float v[3][6];
        #pragma unroll
        for (int kh = 0; kh < 2; kh++) {
            const float* row = &Sc[(py0 + kh) * SSTR + c0 + 3];
            v[kh][0] = row[0];
            float4 q = *(const float4*)(row + 1);
            v[kh][1] = q.x; v[kh][2] = q.y; v[kh][3] = q.z; v[kh][4] = q.w;
            v[kh][5] = row[5];
        }
        const float* srow = &Sc[(py0 + 2) * SSTR + c0 + 3];

        float* ob = out + ((size_t)(b * OUT_CH + g * FPG + chq * 2) * HH
                           + y0 + py0) * WW + tx0 + c0;

        float4 la[8];
        int ppos = 0;

        #pragma unroll
        for (int j = 0; j < 16; j++) {
            // issue next-tile loads at the top of each 4-row chunk
            if (PREF && (j & 3) == 0) {
                ppos = tid + (j >> 2) * 256;
                const int rr  = ppos >> 4;
                const int cc4 = ppos & 15;
                const int gy  = refl(ny0 + rr - 1, HH);
                const float4* p = (const float4*)(xb + (size_t)gy * WW + tx0) + cc4;
                #pragma unroll
                for (int f = 0; f < FPG; f++) la[f] = p[f * PLANE4];
            }

            // stencil row j
            v[2][0] = srow[0];
            {
                float4 q = *(const float4*)(srow + 1);
                v[2][1] = q.x; v[2][2] = q.y; v[2][3] = q.z; v[2][4] = q.w;
            }
            v[2][5] = srow[5];
            srow += SSTR;

            #pragma unroll
            for (int o = 0; o < 2; o++) {
                float4 acc;
                float* ap = (float*)&acc;
                #pragma unroll
                for (int i = 0; i < 4; i++) {
                    float a = 0.f;
                    #pragma unroll
                    for (int kh = 0; kh < 3; kh++)
                        #pragma unroll
                        for (int kw = 0; kw < 3; kw++)
                            a = fmaf(wreg[o][kh * 3 + kw], v[kh][i + kw], a);
                    ap[i] = a;
                }
                *(float4*)(ob + (size_t)o * PLANE + j * WW) = acc;
            }

            #pragma unroll
            for (int q = 0; q < 6; q++) { v[0][q] = v[1][q]; v[1][q] = v[2][q]; }

            // consume the prefetched loads at the bottom of the chunk
            if (PREF && (j & 3) == 3) {
                float4 a = la[0];
                #pragma unroll
                for (int f = 1; f < FPG; f++) {
                    a.x += la[f].x; a.y += la[f].y; a.z += la[f].z; a.w += la[f].w;
                }
                const int rr  = ppos >> 4;
                const int cc4 = ppos & 15;
                *(float4*)&Sn[rr * SSTR + 4 + 4 * cc4] = a;
            }
        }

        // next-tile tail (rows 64,65) + halo columns (small, unoverlapped)
        if (PREF) {
            if (tid < 32) {
                const int pos = 1024 + tid;
                const int r  = pos >> 4;
                const int c4 = pos & 15;
                const int gy = refl(ny0 + r - 1, HH);
                const float4* p = (const float4*)(xb + (size_t)gy * WW + tx0) + c4;
                float4 a = p[0];
                #pragma unroll
                for (int f = 1; f < FPG; f++) {
                    float4 vv = p[f * PLANE4];
                    a.x += vv.x; a.y += vv.y; a.z += vv.z; a.w += vv.w;
                }
                *(float4*)&Sn[r * SSTR + 4 + 4 * c4] = a;
            }
            if (tid < 132) {
                const int r    = tid >> 1;
                const int side = tid & 1;
                const int gy = refl(ny0 + r - 1, HH);
                const int gx = side ? refl(tx0 + 64, WW) : refl(tx0 - 1, WW);
                const float* p = xb + (size_t)gy * WW + gx;
                float a = 0.f;
                #pragma unroll
                for (int f = 0; f < FPG; f++) a += p[f * PLANE];
                Sn[r * SSTR + (side ? 68 : 3)] = a;
            }
        }
        __syncthreads();
    }
}

extern "C" void kernel_launch(void* const* d_in, const int* in_sizes, int n_in,
                              void* d_out, int out_size) {
    const float* x   = (const float*)d_in[0];
    const float* rep = (const float*)d_in[1];
    const float* Wm  = (const float*)d_in[2];
    float* out = (float*)d_out;

    dim3 grid(WW / TW, 8 * 8);                 // 4 bands x 64 (b,g) = 256 CTAs
    dynconv_pipe<<<grid, 256>>>(x, rep, Wm, out);
}